// round 13
// baseline (speedup 1.0000x reference)
#include <cuda_runtime.h>
#include <math.h>

#define BSZ  16
#define N    512
#define TILE 64
#define HALO 11
#define RG   (TILE + 2*HALO)   /* 86 */
#define RP   (RG + 2)          /* 88, multiple of 4 -> 16B rows */
#define EP   24                /* edge-array pitch (max 22 quads + 2 pad) */
#define HID  32
#define NPTS (BSZ*N*N)
#define FOFF 19                /* g_fpad base offset: aligns quad reads */
#define FPAD_EXTRA 8192        /* prefetch overread slack */
/* pad4 + x ping/pong + pad row + 4 edge arrays + tail pad */
#define SMEM_BYTES ((4 + 2*RG*RP + RP + 4 + 4*RG*EP + EP)*4)

typedef unsigned long long ull;

__device__ float  g_x0[NPTS];
__device__ float  g_x1[NPTS];
__device__ __align__(16) float g_fpad[NPTS + FPAD_EXTRA];
__device__ float  g_lfa[NPTS];
__device__ double g_acc[2];

__device__ __forceinline__ ull pk(float a, float b) {
    ull r; asm("mov.b64 %0,{%1,%2};" : "=l"(r) : "f"(a), "f"(b)); return r;
}
__device__ __forceinline__ void upk(ull v, float& a, float& b) {
    asm("mov.b64 {%0,%1},%2;" : "=f"(a), "=f"(b) : "l"(v));
}
__device__ __forceinline__ float lo32(ull v) { float a,b; upk(v,a,b); return a; }
__device__ __forceinline__ ull fma2(ull a, ull b, ull c) {
    ull d; asm("fma.rn.f32x2 %0,%1,%2,%3;" : "=l"(d) : "l"(a), "l"(b), "l"(c)); return d;
}
__device__ __forceinline__ ull mul2(ull a, ull b) {
    ull d; asm("mul.rn.f32x2 %0,%1,%2;" : "=l"(d) : "l"(a), "l"(b)); return d;
}
__device__ __forceinline__ ull add2(ull a, ull b) {
    ull d; asm("add.rn.f32x2 %0,%1,%2;" : "=l"(d) : "l"(a), "l"(b)); return d;
}
__device__ __forceinline__ float tanh_ap(float x) {
    float y; asm("tanh.approx.f32 %0,%1;" : "=f"(y) : "f"(x)); return y;
}
__device__ __forceinline__ float sqrt_ap(float x) {
    float y; asm("sqrt.approx.f32 %0,%1;" : "=f"(y) : "f"(x)); return y;
}

// prep: zero acc + padded f copy + per-point LFA (constant across cycles)
__global__ void __launch_bounds__(256)
prep_kernel(const float* __restrict__ f, const float* __restrict__ kA) {
    if (blockIdx.x == 0 && threadIdx.x < 2) g_acc[threadIdx.x] = 0.0;
    int idx = blockIdx.x * 256 + threadIdx.x;
    int stride = gridDim.x * 256;
    for (int i = idx; i < NPTS + FPAD_EXTRA; i += stride) {
        int s = i - FOFF;
        g_fpad[i] = ((unsigned)s < (unsigned)NPTS) ? f[s] : 0.f;
    }
    const float w2pih = 6.28318530717958647692f / 513.0f;
    for (int i = idx; i < NPTS; i += stride) {
        int b  = i >> 18;               // N*N = 2^18
        int r  = i & (N*N - 1);
        int gy = r >> 9, gx = r & 511;
        const float* kb = kA + b * 9;
        float k00=kb[0],k01=kb[1],k02=kb[2],k10=kb[3],k11=kb[4],k12=kb[5],k20=kb[6],k21=kb[7],k22=kb[8];
        float tau = 0.5f / k11;
        float cA = k00 + k22, cB = k02 + k20, cC = k01 + k21, cD = k10 + k12;
        float sA = k22 - k00, sB = k02 - k20, sC = k21 - k01, sD = k12 - k10;
        float s1, c1, s2, c2;
        __sincosf(w2pih * (float)(gx - 256), &s1, &c1);
        __sincosf(w2pih * (float)(gy - 256), &s2, &c2);
        float ssv = s1*s2, cc = c1*c2, sc = s1*c2, cs = c1*s2;
        float cpp = cc - ssv;
        float cpm = cc + ssv;
        float spp = sc + cs, spm = sc - cs;
        float ReS = cA*cpp + cB*cpm + cC*c2 + cD*c1 + k11;
        float ImS = sA*spp + sB*spm + sC*s2 + sD*s1;
        float Re = fmaf(-tau, ReS, 1.f);
        float Im = -tau * ImS;
        float mg2 = fmaf(Re, Re, Im*Im);
        g_lfa[i] = mg2 * mg2 * sqrt_ap(mg2);   // |1-tau*S|^5
    }
}

// software-pipelined sweep row loop with conflict-free edge arrays
#define SWEEP_Y_LOOP(USE_MASK)                                                  \
    for (int i = 0; i < nrows; ++i) {                                           \
        float4 vb = vb_n; float lbe = lb_n, rbe = rb_n; float4 fv = fv_n;       \
        rp += RP; e3p += EP; e0p += EP; fp += N;                                \
        vb_n = *(const float4*)rp; lb_n = *e3p; rb_n = *e0p;                    \
        fv_n = __ldg((const float4*)fp);                                        \
        ull Lb = pk(lbe, vb.x), Ab = pk(vb.x, vb.y), Db = pk(vb.y, vb.z),       \
            Bb = pk(vb.z, vb.w), Rb = pk(vb.w, rbe);                            \
        ull u1 = fma2(P01, At, pk(fv.x, fv.y));                                 \
        u1 = fma2(P00, Lt, u1); u1 = fma2(P02, Dt, u1);                         \
        ull u2 = mul2(P10, Lm); u2 = fma2(P11, Am, u2); u2 = fma2(P12, Dm, u2); \
        ull u3 = mul2(P20, Lb); u3 = fma2(P21, Ab, u3); u3 = fma2(P22, Db, u3); \
        ull o01 = fma2(TAUP, add2(u1, add2(u2, u3)), Am);                       \
        ull w1 = fma2(P01, Bt, pk(fv.z, fv.w));                                 \
        w1 = fma2(P00, Dt, w1); w1 = fma2(P02, Rt, w1);                         \
        ull w2 = mul2(P10, Dm); w2 = fma2(P11, Bm, w2); w2 = fma2(P12, Rm, w2); \
        ull w3 = mul2(P20, Db); w3 = fma2(P21, Bb, w3); w3 = fma2(P22, Rb, w3); \
        ull o23 = fma2(TAUP, add2(w1, add2(w2, w3)), Bm);                       \
        if (USE_MASK) { o01 = mul2(o01, M01); o23 = mul2(o23, M23); }           \
        float4 ov;                                                              \
        upk(o01, ov.x, ov.y); upk(o23, ov.z, ov.w);                             \
        *(float4*)wp = ov;                                                      \
        *e0w = ov.x; *e3w = ov.w;                                               \
        Lt=Lm; At=Am; Dt=Dm; Bt=Bm; Rt=Rm;                                      \
        Lm=Lb; Am=Ab; Dm=Db; Bm=Bb; Rm=Rb;                                      \
        wp += RP; e0w += EP; e3w += EP;                                         \
    }

__global__ void __launch_bounds__(256, 2)
iter_kernel(int dir, int zero_in,
            const float* __restrict__ f,  const float* __restrict__ kA,
            const float* __restrict__ W1, const float* __restrict__ b1g,
            const float* __restrict__ W2, const float* __restrict__ b2g)
{
    const float* xin  = dir ? g_x1 : g_x0;
    float*       xout = dir ? g_x0 : g_x1;

    extern __shared__ float smraw[];
    float* xsA = smraw + 4;          // 16B-aligned; front pad for [-1] reads
    float* xsB = xsA + RG*RP;
    float* E0A = xsB + RG*RP + RP + 4;   // elem0 copies (right-edge source)
    float* E3A = E0A + RG*EP;            // elem3 copies (left-edge source)
    float* E0B = E3A + RG*EP;
    float* E3B = E0B + RG*EP;

    __shared__ ull sWa[HID], sWb[HID], sBb[HID], sWo[HID];
    __shared__ float ssb2;

    const int b  = blockIdx.z;
    const int tid = threadIdx.y*32 + threadIdx.x;   // 256 threads
    const int gx0v = blockIdx.x * TILE - HALO;
    const int gy0v = blockIdx.y * TILE - HALO;

    const float* kb = kA + b * 9;
    const float k00 = __ldg(kb+0), k01 = __ldg(kb+1), k02 = __ldg(kb+2);
    const float k10 = __ldg(kb+3), k11 = __ldg(kb+4), k12 = __ldg(kb+5);
    const float k20 = __ldg(kb+6), k21 = __ldg(kb+7), k22 = __ldg(kb+8);
    const float tau = 0.5f / k11;
    const float nk00=-k00, nk01=-k01, nk02=-k02;
    const float nk10=-k10, nk11=-k11, nk12=-k12;
    const float nk20=-k20, nk21=-k21, nk22=-k22;
    const ull P00 = pk(nk00,nk00), P01 = pk(nk01,nk01), P02 = pk(nk02,nk02);
    const ull P10 = pk(nk10,nk10), P11 = pk(nk11,nk11), P12 = pk(nk12,nk12);
    const ull P20 = pk(nk20,nk20), P21 = pk(nk21,nk21), P22 = pk(nk22,nk22);
    const ull TAUP = pk(tau, tau);

    if (tid < HID) {
        float wa = W1[2*tid], wb = W1[2*tid+1], bv = b1g[tid], wo = 0.5f*W2[tid];
        sWa[tid] = pk(wa,wa); sWb[tid] = pk(wb,wb);
        sBb[tid] = pk(bv,bv); sWo[tid] = pk(wo,wo);
    } else if (tid == HID) ssb2 = b2g[0];

    const float* fpb = g_fpad + FOFF + b * N * N;

    // ---- fixed mapping (computed ONCE; region fixed across sweeps) ----
    const int xlo = max(1, -gx0v), xhi = min(RG-1, N - gx0v);
    const int ylo = max(1, -gy0v), yhi = min(RG-1, N - gy0v);
    const int px0 = xlo & ~3;
    const int nq  = (xhi - px0 + 3) >> 2;           // 19..22 quads
    const int nstr = 256 / nq;
    const int rpst = (yhi - ylo + nstr - 1) / nstr;
    const int qx = tid % nq;
    const int st = tid / nq;
    const int ys = ylo + st * rpst;
    const int nrows = min(yhi, ys + rpst) - ys;
    const bool active = (st < nstr) && (nrows > 0);
    const int px = px0 + 4*qx;
    const float o0 = ((unsigned)(gx0v + px)     < (unsigned)N) ? 1.f : 0.f;
    const float o1 = ((unsigned)(gx0v + px + 1) < (unsigned)N) ? 1.f : 0.f;
    const float o2 = ((unsigned)(gx0v + px + 2) < (unsigned)N) ? 1.f : 0.f;
    const float o3 = ((unsigned)(gx0v + px + 3) < (unsigned)N) ? 1.f : 0.f;
    const ull M01 = pk(o0, o1), M23 = pk(o2, o3);

    // zero edge arrays (incl. pads)
    for (int idx = tid; idx < 4*RG*EP + EP; idx += 256) E0A[idx] = 0.f;

    // ---- region load (zero-padded outside domain); fill edge arrays; zero pong ----
    const float* fb = f   + b * N * N;
    const float* xb = xin + b * N * N;
    for (int idx = tid; idx < RG*RP; idx += 256) {
        int ly = idx / RP, lx = idx - ly * RP;
        int gy = gy0v + ly, gx = gx0v + lx;
        float xv = 0.f;
        if ((unsigned)gx < N && (unsigned)gy < N) {
            int gi = gy * N + gx;
            xv = zero_in ? (tau * fb[gi]) : xb[gi];
        }
        xsA[ly*RP + lx] = xv;
        xsB[ly*RP + lx] = 0.f;
        int dx = lx - px0;
        if (dx >= 0 && dx < 4*nq) {
            int q = dx >> 2, r = dx & 3;
            if (r == 0)      E0A[ly*EP + q + 1] = xv;
            else if (r == 3) E3A[ly*EP + q + 1] = xv;
        }
    }
    __syncthreads();

    // maskless fast path: region fully inside domain in x
    const bool inx = (gx0v >= 0) && (gx0v + RG <= N);

    // ---- 10 Jacobi sweeps: fixed region, conflict-free edges, pipelined ----
    float* cur = xsA;  float* nxt = xsB;
    float* e0c = E0A;  float* e3c = E3A;
    float* e0n = E0B;  float* e3n = E3B;
    const int s0 = zero_in ? 1 : 0;
    #pragma unroll 1
    for (int s = s0; s < 10; ++s) {
        if (active) {
            const float* rp  = &cur[(ys-1)*RP + px];
            const float* e3p = &e3c[(ys-1)*EP + qx];      // left-edge source
            const float* e0p = &e0c[(ys-1)*EP + qx + 2];  // right-edge source
            float4 vt = *(const float4*)rp;
            float lte = *e3p, rte = *e0p;
            rp += RP; e3p += EP; e0p += EP;
            float4 vm = *(const float4*)rp;
            float lme = *e3p, rme = *e0p;
            rp += RP; e3p += EP; e0p += EP;
            float4 vb_n = *(const float4*)rp;
            float lb_n = *e3p, rb_n = *e0p;
            const float* fp = &fpb[(gy0v + ys)*N + gx0v + px];
            float4 fv_n = __ldg((const float4*)fp);
            float* wp  = &nxt[ys*RP + px];
            float* e3w = &e3n[ys*EP + qx + 1];
            float* e0w = &e0n[ys*EP + qx + 1];
            ull Lt = pk(lte, vt.x), At = pk(vt.x, vt.y), Dt = pk(vt.y, vt.z),
                Bt = pk(vt.z, vt.w), Rt = pk(vt.w, rte);
            ull Lm = pk(lme, vm.x), Am = pk(vm.x, vm.y), Dm = pk(vm.y, vm.z),
                Bm = pk(vm.z, vm.w), Rm = pk(vm.w, rme);
            if (inx) {
                _Pragma("unroll 2")
                SWEEP_Y_LOOP(0)
            } else {
                _Pragma("unroll 2")
                SWEEP_Y_LOOP(1)
            }
        }
        __syncthreads();
        { float* t = cur; cur = nxt; nxt = t; }
        { float* t = e0c; e0c = e0n; e0n = t; }
        { float* t = e3c; e3c = e3n; e3n = t; }
    }
    // cur: x after 10 sweeps, valid on [10,76)

    // ---- residual + MLP epilogue (LFA precomputed) ----
    float* xo = xout + b * N * N;
    const float* lfab = g_lfa + b * N * N;

    // closed form for the linear half of gelu: sum_j 0.5*W2_j*v_j
    float S1 = 0.f, S2 = 0.f, S3 = ssb2;
    #pragma unroll 8
    for (int j = 0; j < HID; ++j) {
        float wo = lo32(sWo[j]);
        S1 = fmaf(wo, lo32(sWa[j]), S1);
        S2 = fmaf(wo, lo32(sWb[j]), S2);
        S3 = fmaf(wo, lo32(sBb[j]), S3);
    }

    const int etx = tid & 15, ety = tid >> 4;   // 16 x 16 logical
    const int ys_e = HALO + ety * 4;

    const ull K1 = pk(0.03567740814f, 0.03567740814f);
    const ull K0 = pk(0.7978845608f,  0.7978845608f);
    const ull Z  = pk(0.f, 0.f);

    #pragma unroll 1
    for (int g = 0; g < 4; ++g) {
        const int cx = HALO + etx + g*16;
        const int gx = gx0v + cx;

        const float* rp0 = &cur[(ys_e-1)*RP + cx];
        float t0 = rp0[-1],   t1 = rp0[0],  t2 = rp0[1];
        float m0 = rp0[RP-1], m1 = rp0[RP], m2 = rp0[RP+1];
        float rl[4], ll[4], xold[4];
        #pragma unroll
        for (int i = 0; i < 4; ++i) {
            const float* nn = rp0 + (i+2)*RP;
            float n0 = nn[-1], n1 = nn[0], n2 = nn[1];
            float a1 = __ldg(&fpb[(gy0v + ys_e + i)*N + gx]);
            a1 = fmaf(nk00,t0,a1); a1 = fmaf(nk01,t1,a1); a1 = fmaf(nk02,t2,a1);
            float a2 = nk10*m0;    a2 = fmaf(nk11,m1,a2); a2 = fmaf(nk12,m2,a2);
            float a3 = nk20*n0;    a3 = fmaf(nk21,n1,a3); a3 = fmaf(nk22,n2,a3);
            rl[i] = a1 + a2 + a3;
            xold[i] = m1;
            ll[i] = __ldg(&lfab[(gy0v + ys_e + i)*N + gx]);
            t0=m0; t1=m1; t2=m2;
            m0=n0; m1=n1; m2=n2;
        }
        ull Rr0 = pk(rl[0], rl[1]), Rr1 = pk(rl[2], rl[3]);
        ull LF0 = pk(ll[0], ll[1]), LF1 = pk(ll[2], ll[3]);
        ull acc20 = Z, acc21 = Z;
        #pragma unroll 4
        for (int j = 0; j < HID; ++j) {
            const ull wa = sWa[j], wb = sWb[j], bb = sBb[j], wo = sWo[j];
            {
                ull v  = fma2(wa, LF0, fma2(wb, Rr0, bb));
                ull v2 = mul2(v, v);
                ull q  = fma2(v2, K1, K0);
                ull t  = mul2(v, q);
                float tl, th; upk(t, tl, th);
                ull T  = pk(tanh_ap(tl), tanh_ap(th));
                acc20 = fma2(mul2(v, wo), T, acc20);
            }
            {
                ull v  = fma2(wa, LF1, fma2(wb, Rr1, bb));
                ull v2 = mul2(v, v);
                ull q  = fma2(v2, K1, K0);
                ull t  = mul2(v, q);
                float tl, th; upk(t, tl, th);
                ull T  = pk(tanh_ap(tl), tanh_ap(th));
                acc21 = fma2(mul2(v, wo), T, acc21);
            }
        }
        float e0,e1,e2,e3;
        upk(acc20, e0, e1); upk(acc21, e2, e3);
        float ev[4] = {e0, e1, e2, e3};
        #pragma unroll
        for (int i = 0; i < 4; ++i) {
            float u = fmaf(S1, ll[i], fmaf(S2, rl[i], S3));
            xo[(gy0v + ys_e + i)*N + gx] = xold[i] + ev[i] + u;
        }
    }
}

__global__ void __launch_bounds__(256)
reduce_kernel(const float* __restrict__ f, const float* __restrict__ kA)
{
    __shared__ float xt[(TILE+2)*(TILE+4)];   // 66 x 68 pitch
    __shared__ float redbuf[16];
    const int b   = blockIdx.z;
    const int tid = threadIdx.y*32 + threadIdx.x;
    const float* xb = g_x1 + b*N*N;           // final x lives in g_x1
    const float* fb = f    + b*N*N;
    const int gx0v = blockIdx.x*TILE - 1;
    const int gy0v = blockIdx.y*TILE - 1;

    for (int idx = tid; idx < 66*66; idx += 256) {
        int ly = idx / 66, lx = idx - ly*66;
        int gy = gy0v + ly, gx = gx0v + lx;
        xt[ly*68 + lx] = ((unsigned)gx < N && (unsigned)gy < N) ? xb[gy*N + gx] : 0.f;
    }
    const float* kb = kA + b * 9;
    const float k00 = __ldg(kb+0), k01 = __ldg(kb+1), k02 = __ldg(kb+2);
    const float k10 = __ldg(kb+3), k11 = __ldg(kb+4), k12 = __ldg(kb+5);
    const float k20 = __ldg(kb+6), k21 = __ldg(kb+7), k22 = __ldg(kb+8);
    __syncthreads();

    float sr = 0.f, sf = 0.f;
    for (int ry = threadIdx.y; ry < TILE; ry += 8) {
        for (int rx = threadIdx.x; rx < TILE; rx += 32) {
            int ly = ry + 1, lx = rx + 1;
            const float* c = &xt[ly*68 + lx];
            float ax = k00*c[-69] + k01*c[-68] + k02*c[-67]
                     + k10*c[-1]  + k11*c[0]   + k12*c[1]
                     + k20*c[67]  + k21*c[68]  + k22*c[69];
            float fv = fb[(gy0v+ly)*N + (gx0v+lx)];
            float r = fv - ax;
            sr = fmaf(r, r, sr);
            sf = fmaf(fv, fv, sf);
        }
    }
    #pragma unroll
    for (int o = 16; o; o >>= 1) {
        sr += __shfl_down_sync(0xffffffffu, sr, o);
        sf += __shfl_down_sync(0xffffffffu, sf, o);
    }
    if (threadIdx.x == 0) { redbuf[threadIdx.y] = sr; redbuf[8+threadIdx.y] = sf; }
    __syncthreads();
    if (tid == 0) {
        float a = 0.f, bb = 0.f;
        #pragma unroll
        for (int i = 0; i < 8; ++i) { a += redbuf[i]; bb += redbuf[8+i]; }
        atomicAdd(&g_acc[0], (double)a);
        atomicAdd(&g_acc[1], (double)bb);
    }
}

__global__ void finalize_kernel(float* out) {
    out[0] = (float)sqrt(g_acc[0] / g_acc[1]);
}

extern "C" void kernel_launch(void* const* d_in, const int* in_sizes, int n_in,
                              void* d_out, int out_size)
{
    // metadata order: f, kernelA, u(unused), W1, b1, W2, b2, epoch(=201 -> K=3)
    const float* f  = (const float*)d_in[0];
    const float* kA = (const float*)d_in[1];
    const float* W1 = (const float*)d_in[3];
    const float* b1 = (const float*)d_in[4];
    const float* W2 = (const float*)d_in[5];
    const float* b2 = (const float*)d_in[6];
    float* out = (float*)d_out;

    cudaFuncSetAttribute(iter_kernel, cudaFuncAttributeMaxDynamicSharedMemorySize, SMEM_BYTES);

    dim3 grid(N/TILE, N/TILE, BSZ);   // (8, 8, 16)
    dim3 blk(32, 8);                  // 256 threads
    dim3 blkR(32, 8);

    prep_kernel<<<2048, 256>>>(f, kA);
    // K = 3 outer cycles; x ping-pongs g_x0 <-> g_x1 (starts at zero)
    iter_kernel<<<grid, blk, SMEM_BYTES>>>(0, 1, f, kA, W1, b1, W2, b2); // 0 -> x1
    iter_kernel<<<grid, blk, SMEM_BYTES>>>(1, 0, f, kA, W1, b1, W2, b2); // x1 -> x0
    iter_kernel<<<grid, blk, SMEM_BYTES>>>(0, 0, f, kA, W1, b1, W2, b2); // x0 -> x1
    reduce_kernel<<<grid, blkR>>>(f, kA);
    finalize_kernel<<<1, 1>>>(out);
}

// round 14
// speedup vs baseline: 1.2411x; 1.2411x over previous
#include <cuda_runtime.h>
#include <math.h>

#define BSZ  16
#define N    512
#define TILE 64
#define HALO 11
#define RG   (TILE + 2*HALO)   /* 86 */
#define RP   (RG + 2)          /* 88, multiple of 4 -> 16B rows */
#define HID  32
#define NPTS (BSZ*N*N)
#define SMEM_BYTES ((4 + 3*RG*RP)*4)   /* 4-float front pad (16B align) */

typedef unsigned long long ull;

__device__ float  g_x0[NPTS];
__device__ float  g_x1[NPTS];
__device__ float  g_lfa[NPTS];
__device__ double g_acc[2];

__global__ void zero_acc_kernel() {
    if (threadIdx.x < 2) g_acc[threadIdx.x] = 0.0;
}

__device__ __forceinline__ ull pk(float a, float b) {
    ull r; asm("mov.b64 %0,{%1,%2};" : "=l"(r) : "f"(a), "f"(b)); return r;
}
__device__ __forceinline__ void upk(ull v, float& a, float& b) {
    asm("mov.b64 {%0,%1},%2;" : "=f"(a), "=f"(b) : "l"(v));
}
__device__ __forceinline__ float lo32(ull v) { float a,b; upk(v,a,b); return a; }
__device__ __forceinline__ ull fma2(ull a, ull b, ull c) {
    ull d; asm("fma.rn.f32x2 %0,%1,%2,%3;" : "=l"(d) : "l"(a), "l"(b), "l"(c)); return d;
}
__device__ __forceinline__ ull mul2(ull a, ull b) {
    ull d; asm("mul.rn.f32x2 %0,%1,%2;" : "=l"(d) : "l"(a), "l"(b)); return d;
}
__device__ __forceinline__ ull add2(ull a, ull b) {
    ull d; asm("add.rn.f32x2 %0,%1,%2;" : "=l"(d) : "l"(a), "l"(b)); return d;
}
__device__ __forceinline__ float tanh_ap(float x) {
    float y; asm("tanh.approx.f32 %0,%1;" : "=f"(y) : "f"(x)); return y;
}
__device__ __forceinline__ float sqrt_ap(float x) {
    float y; asm("sqrt.approx.f32 %0,%1;" : "=f"(y) : "f"(x)); return y;
}

// PHASE 0: first cycle (x starts at 0; computes LFA inline and stores to g_lfa)
// PHASE 1: later cycles (loads LFA from g_lfa)
template<int PHASE>
__global__ void __launch_bounds__(256, 2)
iter_kernel(int dir, int zero_in,
            const float* __restrict__ f,  const float* __restrict__ kA,
            const float* __restrict__ W1, const float* __restrict__ b1g,
            const float* __restrict__ W2, const float* __restrict__ b2g)
{
    const float* xin  = dir ? g_x1 : g_x0;
    float*       xout = dir ? g_x0 : g_x1;

    extern __shared__ float smraw[];
    float* xsA = smraw + 4;          // 16B-aligned; front pad for [-1] reads
    float* xsB = xsA + RG*RP;
    float* fs  = xsB + RG*RP;

    __shared__ ull sWa[HID], sWb[HID], sBb[HID], sWo[HID];
    __shared__ float ssb2;

    const int b  = blockIdx.z;
    const int tid = threadIdx.y*32 + threadIdx.x;   // 256 threads
    const int gx0v = blockIdx.x * TILE - HALO;
    const int gy0v = blockIdx.y * TILE - HALO;

    const float* kb = kA + b * 9;
    const float k00 = __ldg(kb+0), k01 = __ldg(kb+1), k02 = __ldg(kb+2);
    const float k10 = __ldg(kb+3), k11 = __ldg(kb+4), k12 = __ldg(kb+5);
    const float k20 = __ldg(kb+6), k21 = __ldg(kb+7), k22 = __ldg(kb+8);
    const float tau = 0.5f / k11;
    const float nk00=-k00, nk01=-k01, nk02=-k02;
    const float nk10=-k10, nk11=-k11, nk12=-k12;
    const float nk20=-k20, nk21=-k21, nk22=-k22;
    const ull P00 = pk(nk00,nk00), P01 = pk(nk01,nk01), P02 = pk(nk02,nk02);
    const ull P10 = pk(nk10,nk10), P11 = pk(nk11,nk11), P12 = pk(nk12,nk12);
    const ull P20 = pk(nk20,nk20), P21 = pk(nk21,nk21), P22 = pk(nk22,nk22);
    const ull TAUP = pk(tau, tau);

    if (tid < HID) {
        float wa = W1[2*tid], wb = W1[2*tid+1], bv = b1g[tid], wo = 0.5f*W2[tid];
        sWa[tid] = pk(wa,wa); sWb[tid] = pk(wb,wb);
        sBb[tid] = pk(bv,bv); sWo[tid] = pk(wo,wo);
    } else if (tid == HID) ssb2 = b2g[0];

    // ---- region load (zero-padded outside domain); zero pong buffer ----
    const float* fb = f   + b * N * N;
    const float* xb = xin + b * N * N;
    for (int idx = tid; idx < RG*RG; idx += 256) {
        int ly = idx / RG, lx = idx - ly * RG;
        int gy = gy0v + ly, gx = gx0v + lx;
        float xv = 0.f, fv = 0.f;
        if ((unsigned)gx < N && (unsigned)gy < N) {
            int gi = gy * N + gx;
            fv = fb[gi];
            xv = zero_in ? (tau * fv) : xb[gi];
        }
        xsA[ly*RP + lx] = xv;
        fs [ly*RP + lx] = fv;
    }
    for (int idx = tid; idx < RG*RP; idx += 256) xsB[idx] = 0.f;
    __syncthreads();

    // ---- 10 Jacobi sweeps: quad-major thread map (all lanes active) ----
    float* cur = xsA;
    float* nxt = xsB;
    const int s0 = zero_in ? 1 : 0;
    #pragma unroll 1
    for (int s = s0; s < 10; ++s) {
        const int lo = s + 1, hi = RG - 1 - s;
        const int xlo = max(lo, -gx0v), xhi = min(hi, N - gx0v);
        const int ylo = max(lo, -gy0v), yhi = min(hi, N - gy0v);
        const int px0 = xlo & ~3;
        const int nq  = (xhi - px0 + 3) >> 2;       // ~17..22 quads
        const int nstr = 256 / nq;                  // strips
        const int spanY = yhi - ylo;
        const int rpst = (spanY + nstr - 1) / nstr; // rows per strip
        const int qx = tid % nq;
        const int st = tid / nq;
        const int ys = ylo + st * rpst;
        const int ye = min(yhi, ys + rpst);
        if (st < nstr && ys < ye) {
            const int px = px0 + 4*qx;
            const float o0 = ((unsigned)(gx0v + px)     < (unsigned)N) ? 1.f : 0.f;
            const float o1 = ((unsigned)(gx0v + px + 1) < (unsigned)N) ? 1.f : 0.f;
            const float o2 = ((unsigned)(gx0v + px + 2) < (unsigned)N) ? 1.f : 0.f;
            const float o3 = ((unsigned)(gx0v + px + 3) < (unsigned)N) ? 1.f : 0.f;
            const ull M01 = pk(o0, o1), M23 = pk(o2, o3);

            const float* rp = &cur[(ys-1)*RP + px];
            float4 vt = *(const float4*)rp;
            ull Lt = pk(rp[-1], vt.x), At = pk(vt.x, vt.y), Dt = pk(vt.y, vt.z),
                Bt = pk(vt.z, vt.w), Rt = pk(vt.w, rp[4]);
            rp += RP;
            float4 vm = *(const float4*)rp;
            ull Lm = pk(rp[-1], vm.x), Am = pk(vm.x, vm.y), Dm = pk(vm.y, vm.z),
                Bm = pk(vm.z, vm.w), Rm = pk(vm.w, rp[4]);
            rp += RP;
            const float* fp = &fs[ys*RP + px];
            float* wp = &nxt[ys*RP + px];
            #pragma unroll 2
            for (int y = ys; y < ye; ++y) {
                float4 vb = *(const float4*)rp;
                ull Lb = pk(rp[-1], vb.x), Ab = pk(vb.x, vb.y), Db = pk(vb.y, vb.z),
                    Bb = pk(vb.z, vb.w), Rb = pk(vb.w, rp[4]);
                float4 fv = *(const float4*)fp;
                // pair (p0,p1): L=Lx, C=Ax, R=Dx
                ull u1 = fma2(P01, At, pk(fv.x, fv.y));
                u1 = fma2(P00, Lt, u1); u1 = fma2(P02, Dt, u1);
                ull u2 = mul2(P10, Lm); u2 = fma2(P11, Am, u2); u2 = fma2(P12, Dm, u2);
                ull u3 = mul2(P20, Lb); u3 = fma2(P21, Ab, u3); u3 = fma2(P22, Db, u3);
                ull o01 = mul2(fma2(TAUP, add2(u1, add2(u2, u3)), Am), M01);
                // pair (p2,p3): L=Dx, C=Bx, R=Rx
                ull w1 = fma2(P01, Bt, pk(fv.z, fv.w));
                w1 = fma2(P00, Dt, w1); w1 = fma2(P02, Rt, w1);
                ull w2 = mul2(P10, Dm); w2 = fma2(P11, Bm, w2); w2 = fma2(P12, Rm, w2);
                ull w3 = mul2(P20, Db); w3 = fma2(P21, Bb, w3); w3 = fma2(P22, Rb, w3);
                ull o23 = mul2(fma2(TAUP, add2(w1, add2(w2, w3)), Bm), M23);
                float4 ov;
                upk(o01, ov.x, ov.y);
                upk(o23, ov.z, ov.w);
                *(float4*)wp = ov;
                Lt=Lm; At=Am; Dt=Dm; Bt=Bm; Rt=Rm;
                Lm=Lb; Am=Ab; Dm=Db; Bm=Bb; Rm=Rb;
                rp += RP; fp += RP; wp += RP;
            }
        }
        __syncthreads();
        float* t = cur; cur = nxt; nxt = t;
    }
    // cur: x after 10 sweeps, valid on [10,76)

    // ---- residual + LFA + MLP epilogue (16x16 logical) ----
    const float w2pih = 6.28318530717958647692f / 513.0f;
    const float cA = k00 + k22, cB = k02 + k20, cC = k01 + k21, cD = k10 + k12;
    const float sA = k22 - k00, sB = k02 - k20, sC = k21 - k01, sD = k12 - k10;
    float* xo = xout + b * N * N;
    float* lfab = g_lfa + b * N * N;

    // closed form for the linear half of gelu: sum_j 0.5*W2_j*v_j
    float S1 = 0.f, S2 = 0.f, S3 = ssb2;
    #pragma unroll 8
    for (int j = 0; j < HID; ++j) {
        float wo = lo32(sWo[j]);
        S1 = fmaf(wo, lo32(sWa[j]), S1);
        S2 = fmaf(wo, lo32(sWb[j]), S2);
        S3 = fmaf(wo, lo32(sBb[j]), S3);
    }

    const int etx = tid & 15, ety = tid >> 4;   // 16 x 16 logical
    const int ys_e = HALO + ety * 4;
    float s2a[4], c2a[4];
    if (PHASE == 0) {
        #pragma unroll
        for (int i = 0; i < 4; ++i)
            __sincosf(w2pih * (float)(gy0v + ys_e + i - 256), &s2a[i], &c2a[i]);
    }

    const ull K1 = pk(0.03567740814f, 0.03567740814f);
    const ull K0 = pk(0.7978845608f,  0.7978845608f);
    const ull Z  = pk(0.f, 0.f);

    #pragma unroll 1
    for (int g = 0; g < 4; ++g) {
        const int cx = HALO + etx + g*16;
        const int gx = gx0v + cx;
        float s1, c1;
        if (PHASE == 0)
            __sincosf(w2pih * (float)(gx - 256), &s1, &c1);

        const float* rp0 = &cur[(ys_e-1)*RP + cx];
        float t0 = rp0[-1],   t1 = rp0[0],  t2 = rp0[1];
        float m0 = rp0[RP-1], m1 = rp0[RP], m2 = rp0[RP+1];
        float rl[4], ll[4], xold[4];
        #pragma unroll
        for (int i = 0; i < 4; ++i) {
            const float* nn = rp0 + (i+2)*RP;
            float n0 = nn[-1], n1 = nn[0], n2 = nn[1];
            float a1 = fs[(ys_e+i)*RP + cx];
            a1 = fmaf(nk00,t0,a1); a1 = fmaf(nk01,t1,a1); a1 = fmaf(nk02,t2,a1);
            float a2 = nk10*m0;    a2 = fmaf(nk11,m1,a2); a2 = fmaf(nk12,m2,a2);
            float a3 = nk20*n0;    a3 = fmaf(nk21,n1,a3); a3 = fmaf(nk22,n2,a3);
            rl[i] = a1 + a2 + a3;
            xold[i] = m1;
            if (PHASE == 0) {
                float ssv = s1*s2a[i], cc = c1*c2a[i], sc = s1*c2a[i], cs = c1*s2a[i];
                float cpp = cc - ssv, spp = sc + cs;
                float cpm = cc + ssv, spm = sc - cs;
                float ReS = cA*cpp + cB*cpm + cC*c2a[i] + cD*c1 + k11;
                float ImS = sA*spp + sB*spm + sC*s2a[i] + sD*s1;
                float Re = fmaf(-tau, ReS, 1.f);
                float Im = -tau * ImS;
                float mg2 = fmaf(Re, Re, Im*Im);
                ll[i] = mg2 * mg2 * sqrt_ap(mg2);   // |1-tau*S|^5
                lfab[(gy0v + ys_e + i)*N + gx] = ll[i];
            } else {
                ll[i] = __ldg(&lfab[(gy0v + ys_e + i)*N + gx]);
            }
            t0=m0; t1=m1; t2=m2;
            m0=n0; m1=n1; m2=n2;
        }
        ull Rr0 = pk(rl[0], rl[1]), Rr1 = pk(rl[2], rl[3]);
        ull LF0 = pk(ll[0], ll[1]), LF1 = pk(ll[2], ll[3]);
        ull acc20 = Z, acc21 = Z;
        #pragma unroll 4
        for (int j = 0; j < HID; ++j) {
            const ull wa = sWa[j], wb = sWb[j], bb = sBb[j], wo = sWo[j];
            {
                ull v  = fma2(wa, LF0, fma2(wb, Rr0, bb));
                ull v2 = mul2(v, v);
                ull q  = fma2(v2, K1, K0);
                ull t  = mul2(v, q);
                float tl, th; upk(t, tl, th);
                ull T  = pk(tanh_ap(tl), tanh_ap(th));
                acc20 = fma2(mul2(v, wo), T, acc20);
            }
            {
                ull v  = fma2(wa, LF1, fma2(wb, Rr1, bb));
                ull v2 = mul2(v, v);
                ull q  = fma2(v2, K1, K0);
                ull t  = mul2(v, q);
                float tl, th; upk(t, tl, th);
                ull T  = pk(tanh_ap(tl), tanh_ap(th));
                acc21 = fma2(mul2(v, wo), T, acc21);
            }
        }
        float e0,e1,e2,e3;
        upk(acc20, e0, e1); upk(acc21, e2, e3);
        float ev[4] = {e0, e1, e2, e3};
        #pragma unroll
        for (int i = 0; i < 4; ++i) {
            float u = fmaf(S1, ll[i], fmaf(S2, rl[i], S3));
            xo[(gy0v + ys_e + i)*N + gx] = xold[i] + ev[i] + u;
        }
    }
}

__global__ void __launch_bounds__(256)
reduce_kernel(const float* __restrict__ f, const float* __restrict__ kA)
{
    __shared__ float xt[(TILE+2)*(TILE+4)];   // 66 x 68 pitch
    __shared__ float redbuf[16];
    const int b   = blockIdx.z;
    const int tid = threadIdx.y*32 + threadIdx.x;
    const float* xb = g_x1 + b*N*N;           // final x lives in g_x1
    const float* fb = f    + b*N*N;
    const int gx0v = blockIdx.x*TILE - 1;
    const int gy0v = blockIdx.y*TILE - 1;

    for (int idx = tid; idx < 66*66; idx += 256) {
        int ly = idx / 66, lx = idx - ly*66;
        int gy = gy0v + ly, gx = gx0v + lx;
        xt[ly*68 + lx] = ((unsigned)gx < N && (unsigned)gy < N) ? xb[gy*N + gx] : 0.f;
    }
    const float* kb = kA + b * 9;
    const float k00 = __ldg(kb+0), k01 = __ldg(kb+1), k02 = __ldg(kb+2);
    const float k10 = __ldg(kb+3), k11 = __ldg(kb+4), k12 = __ldg(kb+5);
    const float k20 = __ldg(kb+6), k21 = __ldg(kb+7), k22 = __ldg(kb+8);
    __syncthreads();

    float sr = 0.f, sf = 0.f;
    for (int ry = threadIdx.y; ry < TILE; ry += 8) {
        for (int rx = threadIdx.x; rx < TILE; rx += 32) {
            int ly = ry + 1, lx = rx + 1;
            const float* c = &xt[ly*68 + lx];
            float ax = k00*c[-69] + k01*c[-68] + k02*c[-67]
                     + k10*c[-1]  + k11*c[0]   + k12*c[1]
                     + k20*c[67]  + k21*c[68]  + k22*c[69];
            float fv = fb[(gy0v+ly)*N + (gx0v+lx)];
            float r = fv - ax;
            sr = fmaf(r, r, sr);
            sf = fmaf(fv, fv, sf);
        }
    }
    #pragma unroll
    for (int o = 16; o; o >>= 1) {
        sr += __shfl_down_sync(0xffffffffu, sr, o);
        sf += __shfl_down_sync(0xffffffffu, sf, o);
    }
    if (threadIdx.x == 0) { redbuf[threadIdx.y] = sr; redbuf[8+threadIdx.y] = sf; }
    __syncthreads();
    if (tid == 0) {
        float a = 0.f, bb = 0.f;
        #pragma unroll
        for (int i = 0; i < 8; ++i) { a += redbuf[i]; bb += redbuf[8+i]; }
        atomicAdd(&g_acc[0], (double)a);
        atomicAdd(&g_acc[1], (double)bb);
    }
}

__global__ void finalize_kernel(float* out) {
    out[0] = (float)sqrt(g_acc[0] / g_acc[1]);
}

extern "C" void kernel_launch(void* const* d_in, const int* in_sizes, int n_in,
                              void* d_out, int out_size)
{
    // metadata order: f, kernelA, u(unused), W1, b1, W2, b2, epoch(=201 -> K=3)
    const float* f  = (const float*)d_in[0];
    const float* kA = (const float*)d_in[1];
    const float* W1 = (const float*)d_in[3];
    const float* b1 = (const float*)d_in[4];
    const float* W2 = (const float*)d_in[5];
    const float* b2 = (const float*)d_in[6];
    float* out = (float*)d_out;

    cudaFuncSetAttribute(iter_kernel<0>, cudaFuncAttributeMaxDynamicSharedMemorySize, SMEM_BYTES);
    cudaFuncSetAttribute(iter_kernel<1>, cudaFuncAttributeMaxDynamicSharedMemorySize, SMEM_BYTES);

    dim3 grid(N/TILE, N/TILE, BSZ);   // (8, 8, 16)
    dim3 blk(32, 8);                  // 256 threads
    dim3 blkR(32, 8);

    zero_acc_kernel<<<1, 32>>>();
    // K = 3 outer cycles; x ping-pongs g_x0 <-> g_x1 (starts at zero)
    iter_kernel<0><<<grid, blk, SMEM_BYTES>>>(0, 1, f, kA, W1, b1, W2, b2); // 0 -> x1, stores LFA
    iter_kernel<1><<<grid, blk, SMEM_BYTES>>>(1, 0, f, kA, W1, b1, W2, b2); // x1 -> x0, loads LFA
    iter_kernel<1><<<grid, blk, SMEM_BYTES>>>(0, 0, f, kA, W1, b1, W2, b2); // x0 -> x1, loads LFA
    reduce_kernel<<<grid, blkR>>>(f, kA);
    finalize_kernel<<<1, 1>>>(out);
}

// round 15
// speedup vs baseline: 1.2540x; 1.0104x over previous
#include <cuda_runtime.h>
#include <math.h>

#define BSZ  16
#define N    512
#define TILE 64
#define HID  32
#define NPTS (BSZ*N*N)

typedef unsigned long long ull;

__device__ float  g_x0[NPTS];
__device__ float  g_x1[NPTS];
__device__ float  g_lfa[NPTS];
__device__ double g_acc[2];

__global__ void zero_acc_kernel() {
    if (threadIdx.x < 2) g_acc[threadIdx.x] = 0.0;
}

__device__ __forceinline__ ull pk(float a, float b) {
    ull r; asm("mov.b64 %0,{%1,%2};" : "=l"(r) : "f"(a), "f"(b)); return r;
}
__device__ __forceinline__ void upk(ull v, float& a, float& b) {
    asm("mov.b64 {%0,%1},%2;" : "=f"(a), "=f"(b) : "l"(v));
}
__device__ __forceinline__ float lo32(ull v) { float a,b; upk(v,a,b); return a; }
__device__ __forceinline__ ull fma2(ull a, ull b, ull c) {
    ull d; asm("fma.rn.f32x2 %0,%1,%2,%3;" : "=l"(d) : "l"(a), "l"(b), "l"(c)); return d;
}
__device__ __forceinline__ ull mul2(ull a, ull b) {
    ull d; asm("mul.rn.f32x2 %0,%1,%2;" : "=l"(d) : "l"(a), "l"(b)); return d;
}
__device__ __forceinline__ ull add2(ull a, ull b) {
    ull d; asm("add.rn.f32x2 %0,%1,%2;" : "=l"(d) : "l"(a), "l"(b)); return d;
}
__device__ __forceinline__ float tanh_ap(float x) {
    float y; asm("tanh.approx.f32 %0,%1;" : "=f"(y) : "f"(x)); return y;
}
__device__ __forceinline__ float sqrt_ap(float x) {
    float y; asm("sqrt.approx.f32 %0,%1;" : "=f"(y) : "f"(x)); return y;
}

// block-wide sum of v into g_acc[slot]
__device__ __forceinline__ void block_reduce_add(float v, int slot, int tid) {
    __shared__ float red[8];
    #pragma unroll
    for (int o = 16; o; o >>= 1) v += __shfl_down_sync(0xffffffffu, v, o);
    if ((tid & 31) == 0) red[tid >> 5] = v;
    __syncthreads();
    if (tid == 0) {
        float s = 0.f;
        #pragma unroll
        for (int i = 0; i < 8; ++i) s += red[i];
        atomicAdd(&g_acc[slot], (double)s);
    }
}

// PHASE 0: cycle 1 (x=0 start; computes+stores LFA; accumulates ||f||^2)
// PHASE 1: cycle 2 (loads LFA; writes x to global)
// PHASE 2: cycle 3 (HALO=12; corrected x in smem ring-extended; fused ||r||^2; no x output)
template<int PHASE>
__global__ void __launch_bounds__(256, 2)
iter_kernel(int dir, int zero_in,
            const float* __restrict__ f,  const float* __restrict__ kA,
            const float* __restrict__ W1, const float* __restrict__ b1g,
            const float* __restrict__ W2, const float* __restrict__ b2g)
{
    constexpr int HL  = (PHASE == 2) ? 12 : 11;
    constexpr int RGv = TILE + 2*HL;            // 86 or 88
    constexpr int RPv = (RGv + 2 + 3) & ~3;     // 88 or 92

    const float* xin  = dir ? g_x1 : g_x0;
    float*       xout = dir ? g_x0 : g_x1;

    extern __shared__ float smraw[];
    float* xsA = smraw + 4;          // 16B-aligned; front pad for [-1] reads
    float* xsB = xsA + RGv*RPv;
    float* fs  = xsB + RGv*RPv;

    __shared__ ull sWa[HID], sWb[HID], sBb[HID], sWo[HID];
    __shared__ float ssb2;

    const int b  = blockIdx.z;
    const int tid = threadIdx.y*32 + threadIdx.x;   // 256 threads
    const int gx0v = blockIdx.x * TILE - HL;
    const int gy0v = blockIdx.y * TILE - HL;

    const float* kb = kA + b * 9;
    const float k00 = __ldg(kb+0), k01 = __ldg(kb+1), k02 = __ldg(kb+2);
    const float k10 = __ldg(kb+3), k11 = __ldg(kb+4), k12 = __ldg(kb+5);
    const float k20 = __ldg(kb+6), k21 = __ldg(kb+7), k22 = __ldg(kb+8);
    const float tau = 0.5f / k11;
    const float nk00=-k00, nk01=-k01, nk02=-k02;
    const float nk10=-k10, nk11=-k11, nk12=-k12;
    const float nk20=-k20, nk21=-k21, nk22=-k22;
    const ull P00 = pk(nk00,nk00), P01 = pk(nk01,nk01), P02 = pk(nk02,nk02);
    const ull P10 = pk(nk10,nk10), P11 = pk(nk11,nk11), P12 = pk(nk12,nk12);
    const ull P20 = pk(nk20,nk20), P21 = pk(nk21,nk21), P22 = pk(nk22,nk22);
    const ull TAUP = pk(tau, tau);

    if (tid < HID) {
        float wa = W1[2*tid], wb = W1[2*tid+1], bv = b1g[tid], wo = 0.5f*W2[tid];
        sWa[tid] = pk(wa,wa); sWb[tid] = pk(wb,wb);
        sBb[tid] = pk(bv,bv); sWo[tid] = pk(wo,wo);
    } else if (tid == HID) ssb2 = b2g[0];

    // ---- region load (zero-padded outside domain); zero pong buffer ----
    const float* fb = f   + b * N * N;
    const float* xb = xin + b * N * N;
    for (int idx = tid; idx < RGv*RGv; idx += 256) {
        int ly = idx / RGv, lx = idx - ly * RGv;
        int gy = gy0v + ly, gx = gx0v + lx;
        float xv = 0.f, fv = 0.f;
        if ((unsigned)gx < N && (unsigned)gy < N) {
            int gi = gy * N + gx;
            fv = fb[gi];
            xv = zero_in ? (tau * fv) : xb[gi];
        }
        xsA[ly*RPv + lx] = xv;
        fs [ly*RPv + lx] = fv;
    }
    for (int idx = tid; idx < RGv*RPv; idx += 256) xsB[idx] = 0.f;
    __syncthreads();

    // ---- 10 Jacobi sweeps: quad-major thread map ----
    float* cur = xsA;
    float* nxt = xsB;
    const int s0 = zero_in ? 1 : 0;
    #pragma unroll 1
    for (int s = s0; s < 10; ++s) {
        const int lo = s + 1, hi = RGv - 1 - s;
        const int xlo = max(lo, -gx0v), xhi = min(hi, N - gx0v);
        const int ylo = max(lo, -gy0v), yhi = min(hi, N - gy0v);
        const int px0 = xlo & ~3;
        const int nq  = (xhi - px0 + 3) >> 2;
        const int nstr = 256 / nq;
        const int spanY = yhi - ylo;
        const int rpst = (spanY + nstr - 1) / nstr;
        const int qx = tid % nq;
        const int st = tid / nq;
        const int ys = ylo + st * rpst;
        const int ye = min(yhi, ys + rpst);
        if (st < nstr && ys < ye) {
            const int px = px0 + 4*qx;
            const float o0 = ((unsigned)(gx0v + px)     < (unsigned)N) ? 1.f : 0.f;
            const float o1 = ((unsigned)(gx0v + px + 1) < (unsigned)N) ? 1.f : 0.f;
            const float o2 = ((unsigned)(gx0v + px + 2) < (unsigned)N) ? 1.f : 0.f;
            const float o3 = ((unsigned)(gx0v + px + 3) < (unsigned)N) ? 1.f : 0.f;
            const ull M01 = pk(o0, o1), M23 = pk(o2, o3);

            const float* rp = &cur[(ys-1)*RPv + px];
            float4 vt = *(const float4*)rp;
            ull Lt = pk(rp[-1], vt.x), At = pk(vt.x, vt.y), Dt = pk(vt.y, vt.z),
                Bt = pk(vt.z, vt.w), Rt = pk(vt.w, rp[4]);
            rp += RPv;
            float4 vm = *(const float4*)rp;
            ull Lm = pk(rp[-1], vm.x), Am = pk(vm.x, vm.y), Dm = pk(vm.y, vm.z),
                Bm = pk(vm.z, vm.w), Rm = pk(vm.w, rp[4]);
            rp += RPv;
            const float* fp = &fs[ys*RPv + px];
            float* wp = &nxt[ys*RPv + px];
            #pragma unroll 2
            for (int y = ys; y < ye; ++y) {
                float4 vb = *(const float4*)rp;
                ull Lb = pk(rp[-1], vb.x), Ab = pk(vb.x, vb.y), Db = pk(vb.y, vb.z),
                    Bb = pk(vb.z, vb.w), Rb = pk(vb.w, rp[4]);
                float4 fv = *(const float4*)fp;
                ull u1 = fma2(P01, At, pk(fv.x, fv.y));
                u1 = fma2(P00, Lt, u1); u1 = fma2(P02, Dt, u1);
                ull u2 = mul2(P10, Lm); u2 = fma2(P11, Am, u2); u2 = fma2(P12, Dm, u2);
                ull u3 = mul2(P20, Lb); u3 = fma2(P21, Ab, u3); u3 = fma2(P22, Db, u3);
                ull o01 = mul2(fma2(TAUP, add2(u1, add2(u2, u3)), Am), M01);
                ull w1 = fma2(P01, Bt, pk(fv.z, fv.w));
                w1 = fma2(P00, Dt, w1); w1 = fma2(P02, Rt, w1);
                ull w2 = mul2(P10, Dm); w2 = fma2(P11, Bm, w2); w2 = fma2(P12, Rm, w2);
                ull w3 = mul2(P20, Db); w3 = fma2(P21, Bb, w3); w3 = fma2(P22, Rb, w3);
                ull o23 = mul2(fma2(TAUP, add2(w1, add2(w2, w3)), Bm), M23);
                float4 ov;
                upk(o01, ov.x, ov.y);
                upk(o23, ov.z, ov.w);
                *(float4*)wp = ov;
                Lt=Lm; At=Am; Dt=Dm; Bt=Bm; Rt=Rm;
                Lm=Lb; Am=Ab; Db=Db; Dm=Db; Bm=Bb; Rm=Rb;
                rp += RPv; fp += RPv; wp += RPv;
            }
        }
        __syncthreads();
        float* t = cur; cur = nxt; nxt = t;
    }
    // cur: x after 10 sweeps, valid on [10, RGv-10)

    // ---- epilogue ----
    const float w2pih = 6.28318530717958647692f / 513.0f;
    const float cA = k00 + k22, cB = k02 + k20, cC = k01 + k21, cD = k10 + k12;
    const float sA = k22 - k00, sB = k02 - k20, sC = k21 - k01, sD = k12 - k10;
    float* xo = xout + b * N * N;
    float* lfab = g_lfa + b * N * N;

    float S1 = 0.f, S2 = 0.f, S3 = ssb2;
    #pragma unroll 8
    for (int j = 0; j < HID; ++j) {
        float wo = lo32(sWo[j]);
        S1 = fmaf(wo, lo32(sWa[j]), S1);
        S2 = fmaf(wo, lo32(sWb[j]), S2);
        S3 = fmaf(wo, lo32(sBb[j]), S3);
    }

    const int etx = tid & 15, ety = tid >> 4;   // 16 x 16 logical
    const int ys_e = HL + ety * 4;
    float s2a[4], c2a[4];
    if (PHASE == 0) {
        #pragma unroll
        for (int i = 0; i < 4; ++i)
            __sincosf(w2pih * (float)(gy0v + ys_e + i - 256), &s2a[i], &c2a[i]);
    }

    const ull K1 = pk(0.03567740814f, 0.03567740814f);
    const ull K0 = pk(0.7978845608f,  0.7978845608f);
    const ull Z  = pk(0.f, 0.f);
    float facc = 0.f;   // PHASE 0: ||f||^2 partial

    #pragma unroll 1
    for (int g = 0; g < 4; ++g) {
        const int cx = HL + etx + g*16;
        const int gx = gx0v + cx;
        float s1, c1;
        if (PHASE == 0)
            __sincosf(w2pih * (float)(gx - 256), &s1, &c1);

        const float* rp0 = &cur[(ys_e-1)*RPv + cx];
        float t0 = rp0[-1],    t1 = rp0[0],   t2 = rp0[1];
        float m0 = rp0[RPv-1], m1 = rp0[RPv], m2 = rp0[RPv+1];
        float rl[4], ll[4], xold[4];
        #pragma unroll
        for (int i = 0; i < 4; ++i) {
            const float* nn = rp0 + (i+2)*RPv;
            float n0 = nn[-1], n1 = nn[0], n2 = nn[1];
            float fv_ = fs[(ys_e+i)*RPv + cx];
            if (PHASE == 0) facc = fmaf(fv_, fv_, facc);
            float a1 = fv_;
            a1 = fmaf(nk00,t0,a1); a1 = fmaf(nk01,t1,a1); a1 = fmaf(nk02,t2,a1);
            float a2 = nk10*m0;    a2 = fmaf(nk11,m1,a2); a2 = fmaf(nk12,m2,a2);
            float a3 = nk20*n0;    a3 = fmaf(nk21,n1,a3); a3 = fmaf(nk22,n2,a3);
            rl[i] = a1 + a2 + a3;
            xold[i] = m1;
            if (PHASE == 0) {
                float ssv = s1*s2a[i], cc = c1*c2a[i], sc = s1*c2a[i], cs = c1*s2a[i];
                float cpp = cc - ssv, spp = sc + cs;
                float cpm = cc + ssv, spm = sc - cs;
                float ReS = cA*cpp + cB*cpm + cC*c2a[i] + cD*c1 + k11;
                float ImS = sA*spp + sB*spm + sC*s2a[i] + sD*s1;
                float Re = fmaf(-tau, ReS, 1.f);
                float Im = -tau * ImS;
                float mg2 = fmaf(Re, Re, Im*Im);
                ll[i] = mg2 * mg2 * sqrt_ap(mg2);   // |1-tau*S|^5
                lfab[(gy0v + ys_e + i)*N + gx] = ll[i];
            } else {
                ll[i] = __ldg(&lfab[(gy0v + ys_e + i)*N + gx]);
            }
            t0=m0; t1=m1; t2=m2;
            m0=n0; m1=n1; m2=n2;
        }
        ull Rr0 = pk(rl[0], rl[1]), Rr1 = pk(rl[2], rl[3]);
        ull LF0 = pk(ll[0], ll[1]), LF1 = pk(ll[2], ll[3]);
        ull acc20 = Z, acc21 = Z;
        #pragma unroll 4
        for (int j = 0; j < HID; ++j) {
            const ull wa = sWa[j], wb = sWb[j], bb = sBb[j], wo = sWo[j];
            {
                ull v  = fma2(wa, LF0, fma2(wb, Rr0, bb));
                ull v2 = mul2(v, v);
                ull q  = fma2(v2, K1, K0);
                ull t  = mul2(v, q);
                float tl, th; upk(t, tl, th);
                ull T  = pk(tanh_ap(tl), tanh_ap(th));
                acc20 = fma2(mul2(v, wo), T, acc20);
            }
            {
                ull v  = fma2(wa, LF1, fma2(wb, Rr1, bb));
                ull v2 = mul2(v, v);
                ull q  = fma2(v2, K1, K0);
                ull t  = mul2(v, q);
                float tl, th; upk(t, tl, th);
                ull T  = pk(tanh_ap(tl), tanh_ap(th));
                acc21 = fma2(mul2(v, wo), T, acc21);
            }
        }
        float e0,e1,e2,e3;
        upk(acc20, e0, e1); upk(acc21, e2, e3);
        float ev[4] = {e0, e1, e2, e3};
        #pragma unroll
        for (int i = 0; i < 4; ++i) {
            float u = fmaf(S1, ll[i], fmaf(S2, rl[i], S3));
            float xc = xold[i] + ev[i] + u;
            if (PHASE == 2) nxt[(ys_e + i)*RPv + cx] = xc;
            else            xo[(gy0v + ys_e + i)*N + gx] = xc;
        }
    }

    if (PHASE == 0) {
        __syncthreads();
        block_reduce_add(facc, 1, tid);
        return;
    }

    if (PHASE == 2) {
        // ---- ring pass: corrected x on border of [HL-1, HL+65)^2 (260 pts) ----
        const float K0s = 0.7978845608f, K1s = 0.03567740814f;
        for (int i = tid; i < 260; i += 256) {
            int lx, ly;
            if (i < 66)       { lx = HL-1;            ly = HL-1 + i; }
            else if (i < 132) { lx = HL+64;           ly = HL-1 + (i-66); }
            else if (i < 196) { lx = HL + (i-132);    ly = HL-1; }
            else              { lx = HL + (i-196);    ly = HL+64; }
            int gx = gx0v + lx, gy = gy0v + ly;
            float xc = 0.f;
            if ((unsigned)gx < N && (unsigned)gy < N) {
                const float* c = &cur[ly*RPv + lx];
                float a1 = fs[ly*RPv + lx];
                a1 = fmaf(nk00, c[-RPv-1], a1); a1 = fmaf(nk01, c[-RPv], a1); a1 = fmaf(nk02, c[-RPv+1], a1);
                a1 = fmaf(nk10, c[-1],     a1); a1 = fmaf(nk11, c[0],    a1); a1 = fmaf(nk12, c[1],     a1);
                a1 = fmaf(nk20, c[RPv-1],  a1); a1 = fmaf(nk21, c[RPv],  a1); a1 = fmaf(nk22, c[RPv+1],  a1);
                float r = a1;
                float lf = __ldg(&lfab[gy*N + gx]);
                float acc = fmaf(S1, lf, fmaf(S2, r, S3));
                #pragma unroll 4
                for (int j = 0; j < HID; ++j) {
                    float v = fmaf(lo32(sWa[j]), lf, fmaf(lo32(sWb[j]), r, lo32(sBb[j])));
                    float t = v * fmaf(K1s * v, v, K0s);
                    acc = fmaf(lo32(sWo[j]) * v, tanh_ap(t), acc);
                }
                xc = c[0] + acc;
            }
            nxt[ly*RPv + lx] = xc;
        }
        __syncthreads();

        // ---- fused final residual: ||f - A x_corrected||^2 over tile interior ----
        float racc = 0.f;
        #pragma unroll 1
        for (int g = 0; g < 4; ++g) {
            const int lx = HL + etx + g*16;
            #pragma unroll
            for (int i = 0; i < 4; ++i) {
                const int ly = HL + ety*4 + i;
                const float* c = &nxt[ly*RPv + lx];
                float a1 = fs[ly*RPv + lx];
                a1 = fmaf(nk00, c[-RPv-1], a1); a1 = fmaf(nk01, c[-RPv], a1); a1 = fmaf(nk02, c[-RPv+1], a1);
                a1 = fmaf(nk10, c[-1],     a1); a1 = fmaf(nk11, c[0],    a1); a1 = fmaf(nk12, c[1],     a1);
                a1 = fmaf(nk20, c[RPv-1],  a1); a1 = fmaf(nk21, c[RPv],  a1); a1 = fmaf(nk22, c[RPv+1],  a1);
                racc = fmaf(a1, a1, racc);
            }
        }
        __syncthreads();
        block_reduce_add(racc, 0, tid);
    }
}

__global__ void finalize_kernel(float* out) {
    out[0] = (float)sqrt(g_acc[0] / g_acc[1]);
}

extern "C" void kernel_launch(void* const* d_in, const int* in_sizes, int n_in,
                              void* d_out, int out_size)
{
    // metadata order: f, kernelA, u(unused), W1, b1, W2, b2, epoch(=201 -> K=3)
    const float* f  = (const float*)d_in[0];
    const float* kA = (const float*)d_in[1];
    const float* W1 = (const float*)d_in[3];
    const float* b1 = (const float*)d_in[4];
    const float* W2 = (const float*)d_in[5];
    const float* b2 = (const float*)d_in[6];
    float* out = (float*)d_out;

    const int smem01 = (4 + 3*86*88)*4;   // HALO 11
    const int smem2  = (4 + 3*88*92)*4;   // HALO 12

    cudaFuncSetAttribute(iter_kernel<0>, cudaFuncAttributeMaxDynamicSharedMemorySize, smem01);
    cudaFuncSetAttribute(iter_kernel<1>, cudaFuncAttributeMaxDynamicSharedMemorySize, smem01);
    cudaFuncSetAttribute(iter_kernel<2>, cudaFuncAttributeMaxDynamicSharedMemorySize, smem2);

    dim3 grid(N/TILE, N/TILE, BSZ);   // (8, 8, 16)
    dim3 blk(32, 8);                  // 256 threads

    zero_acc_kernel<<<1, 32>>>();
    // K = 3 outer cycles; x ping-pongs g_x0 <-> g_x1 (starts at zero)
    iter_kernel<0><<<grid, blk, smem01>>>(0, 1, f, kA, W1, b1, W2, b2); // 0 -> x1 (+LFA, +||f||^2)
    iter_kernel<1><<<grid, blk, smem01>>>(1, 0, f, kA, W1, b1, W2, b2); // x1 -> x0
    iter_kernel<2><<<grid, blk, smem2 >>>(0, 0, f, kA, W1, b1, W2, b2); // x0 -> fused ||r||^2
    finalize_kernel<<<1, 1>>>(out);
}

// round 16
// speedup vs baseline: 1.2617x; 1.0061x over previous
#include <cuda_runtime.h>
#include <math.h>

#define BSZ  16
#define N    512
#define TILE 64
#define HID  32
#define NPTS (BSZ*N*N)

typedef unsigned long long ull;

__device__ float  g_x0[NPTS];
__device__ float  g_x1[NPTS];
__device__ double g_acc[2];

__global__ void zero_acc_kernel() {
    if (threadIdx.x < 2) g_acc[threadIdx.x] = 0.0;
}

__device__ __forceinline__ ull pk(float a, float b) {
    ull r; asm("mov.b64 %0,{%1,%2};" : "=l"(r) : "f"(a), "f"(b)); return r;
}
__device__ __forceinline__ void upk(ull v, float& a, float& b) {
    asm("mov.b64 {%0,%1},%2;" : "=f"(a), "=f"(b) : "l"(v));
}
__device__ __forceinline__ float lo32(ull v) { float a,b; upk(v,a,b); return a; }
__device__ __forceinline__ ull fma2(ull a, ull b, ull c) {
    ull d; asm("fma.rn.f32x2 %0,%1,%2,%3;" : "=l"(d) : "l"(a), "l"(b), "l"(c)); return d;
}
__device__ __forceinline__ ull mul2(ull a, ull b) {
    ull d; asm("mul.rn.f32x2 %0,%1,%2;" : "=l"(d) : "l"(a), "l"(b)); return d;
}
__device__ __forceinline__ ull add2(ull a, ull b) {
    ull d; asm("add.rn.f32x2 %0,%1,%2;" : "=l"(d) : "l"(a), "l"(b)); return d;
}
__device__ __forceinline__ float tanh_ap(float x) {
    float y; asm("tanh.approx.f32 %0,%1;" : "=f"(y) : "f"(x)); return y;
}
__device__ __forceinline__ float sqrt_ap(float x) {
    float y; asm("sqrt.approx.f32 %0,%1;" : "=f"(y) : "f"(x)); return y;
}

// block-wide sum of v into g_acc[slot]
__device__ __forceinline__ void block_reduce_add(float v, int slot, int tid) {
    __shared__ float red[8];
    #pragma unroll
    for (int o = 16; o; o >>= 1) v += __shfl_down_sync(0xffffffffu, v, o);
    if ((tid & 31) == 0) red[tid >> 5] = v;
    __syncthreads();
    if (tid == 0) {
        float s = 0.f;
        #pragma unroll
        for (int i = 0; i < 8; ++i) s += red[i];
        atomicAdd(&g_acc[slot], (double)s);
    }
}

// PHASE 0: cycle 1 (x=0 start; accumulates ||f||^2)
// PHASE 1: cycle 2 (writes x to global)
// PHASE 2: cycle 3 (HALO=12; corrected x kept in smem; fused ||r||^2; no x output)
template<int PHASE>
__global__ void __launch_bounds__(256, 2)
iter_kernel(int dir, int zero_in,
            const float* __restrict__ f,  const float* __restrict__ kA,
            const float* __restrict__ W1, const float* __restrict__ b1g,
            const float* __restrict__ W2, const float* __restrict__ b2g)
{
    constexpr int HL  = (PHASE == 2) ? 12 : 11;
    constexpr int RGv = TILE + 2*HL;            // 86 or 88
    constexpr int RPv = (RGv + 2 + 3) & ~3;     // 88 or 92

    const float* xin  = dir ? g_x1 : g_x0;
    float*       xout = dir ? g_x0 : g_x1;

    extern __shared__ float smraw[];
    float* xsA = smraw + 4;          // 16B-aligned; front pad for [-1] reads
    float* xsB = xsA + RGv*RPv;
    float* fs  = xsB + RGv*RPv;

    __shared__ ull sWa[HID], sWb[HID], sBb[HID], sWo[HID];
    __shared__ float ssb2;

    const int b  = blockIdx.z;
    const int tid = threadIdx.y*32 + threadIdx.x;   // 256 threads
    const int gx0v = blockIdx.x * TILE - HL;
    const int gy0v = blockIdx.y * TILE - HL;

    const float* kb = kA + b * 9;
    const float k00 = __ldg(kb+0), k01 = __ldg(kb+1), k02 = __ldg(kb+2);
    const float k10 = __ldg(kb+3), k11 = __ldg(kb+4), k12 = __ldg(kb+5);
    const float k20 = __ldg(kb+6), k21 = __ldg(kb+7), k22 = __ldg(kb+8);
    const float tau = 0.5f / k11;
    const float nk00=-k00, nk01=-k01, nk02=-k02;
    const float nk10=-k10, nk11=-k11, nk12=-k12;
    const float nk20=-k20, nk21=-k21, nk22=-k22;
    const ull P00 = pk(nk00,nk00), P01 = pk(nk01,nk01), P02 = pk(nk02,nk02);
    const ull P10 = pk(nk10,nk10), P11 = pk(nk11,nk11), P12 = pk(nk12,nk12);
    const ull P20 = pk(nk20,nk20), P21 = pk(nk21,nk21), P22 = pk(nk22,nk22);
    const ull TAUP = pk(tau, tau);

    if (tid < HID) {
        float wa = W1[2*tid], wb = W1[2*tid+1], bv = b1g[tid], wo = 0.5f*W2[tid];
        sWa[tid] = pk(wa,wa); sWb[tid] = pk(wb,wb);
        sBb[tid] = pk(bv,bv); sWo[tid] = pk(wo,wo);
    } else if (tid == HID) ssb2 = b2g[0];

    // ---- region load (zero-padded outside domain); zero pong buffer ----
    const float* fb = f   + b * N * N;
    const float* xb = xin + b * N * N;
    for (int idx = tid; idx < RGv*RGv; idx += 256) {
        int ly = idx / RGv, lx = idx - ly * RGv;
        int gy = gy0v + ly, gx = gx0v + lx;
        float xv = 0.f, fv = 0.f;
        if ((unsigned)gx < N && (unsigned)gy < N) {
            int gi = gy * N + gx;
            fv = fb[gi];
            xv = zero_in ? (tau * fv) : xb[gi];
        }
        xsA[ly*RPv + lx] = xv;
        fs [ly*RPv + lx] = fv;
    }
    for (int idx = tid; idx < RGv*RPv; idx += 256) xsB[idx] = 0.f;
    __syncthreads();

    // ---- 10 Jacobi sweeps: quad-major thread map ----
    float* cur = xsA;
    float* nxt = xsB;
    const int s0 = zero_in ? 1 : 0;
    #pragma unroll 1
    for (int s = s0; s < 10; ++s) {
        const int lo = s + 1, hi = RGv - 1 - s;
        const int xlo = max(lo, -gx0v), xhi = min(hi, N - gx0v);
        const int ylo = max(lo, -gy0v), yhi = min(hi, N - gy0v);
        const int px0 = xlo & ~3;
        const int nq  = (xhi - px0 + 3) >> 2;
        const int nstr = 256 / nq;
        const int spanY = yhi - ylo;
        const int rpst = (spanY + nstr - 1) / nstr;
        const int qx = tid % nq;
        const int st = tid / nq;
        const int ys = ylo + st * rpst;
        const int ye = min(yhi, ys + rpst);
        if (st < nstr && ys < ye) {
            const int px = px0 + 4*qx;
            const float o0 = ((unsigned)(gx0v + px)     < (unsigned)N) ? 1.f : 0.f;
            const float o1 = ((unsigned)(gx0v + px + 1) < (unsigned)N) ? 1.f : 0.f;
            const float o2 = ((unsigned)(gx0v + px + 2) < (unsigned)N) ? 1.f : 0.f;
            const float o3 = ((unsigned)(gx0v + px + 3) < (unsigned)N) ? 1.f : 0.f;
            const ull M01 = pk(o0, o1), M23 = pk(o2, o3);

            const float* rp = &cur[(ys-1)*RPv + px];
            float4 vt = *(const float4*)rp;
            ull Lt = pk(rp[-1], vt.x), At = pk(vt.x, vt.y), Dt = pk(vt.y, vt.z),
                Bt = pk(vt.z, vt.w), Rt = pk(vt.w, rp[4]);
            rp += RPv;
            float4 vm = *(const float4*)rp;
            ull Lm = pk(rp[-1], vm.x), Am = pk(vm.x, vm.y), Dm = pk(vm.y, vm.z),
                Bm = pk(vm.z, vm.w), Rm = pk(vm.w, rp[4]);
            rp += RPv;
            const float* fp = &fs[ys*RPv + px];
            float* wp = &nxt[ys*RPv + px];
            #pragma unroll 2
            for (int y = ys; y < ye; ++y) {
                float4 vb = *(const float4*)rp;
                ull Lb = pk(rp[-1], vb.x), Ab = pk(vb.x, vb.y), Db = pk(vb.y, vb.z),
                    Bb = pk(vb.z, vb.w), Rb = pk(vb.w, rp[4]);
                float4 fv = *(const float4*)fp;
                ull u1 = fma2(P01, At, pk(fv.x, fv.y));
                u1 = fma2(P00, Lt, u1); u1 = fma2(P02, Dt, u1);
                ull u2 = mul2(P10, Lm); u2 = fma2(P11, Am, u2); u2 = fma2(P12, Dm, u2);
                ull u3 = mul2(P20, Lb); u3 = fma2(P21, Ab, u3); u3 = fma2(P22, Db, u3);
                ull o01 = mul2(fma2(TAUP, add2(u1, add2(u2, u3)), Am), M01);
                ull w1 = fma2(P01, Bt, pk(fv.z, fv.w));
                w1 = fma2(P00, Dt, w1); w1 = fma2(P02, Rt, w1);
                ull w2 = mul2(P10, Dm); w2 = fma2(P11, Bm, w2); w2 = fma2(P12, Rm, w2);
                ull w3 = mul2(P20, Db); w3 = fma2(P21, Bb, w3); w3 = fma2(P22, Rb, w3);
                ull o23 = mul2(fma2(TAUP, add2(w1, add2(w2, w3)), Bm), M23);
                float4 ov;
                upk(o01, ov.x, ov.y);
                upk(o23, ov.z, ov.w);
                *(float4*)wp = ov;
                Lt=Lm; At=Am; Dt=Dm; Bt=Bm; Rt=Rm;
                Lm=Lb; Am=Ab; Dm=Db; Bm=Bb; Rm=Rb;
                rp += RPv; fp += RPv; wp += RPv;
            }
        }
        __syncthreads();
        float* t = cur; cur = nxt; nxt = t;
    }
    // cur: x after 10 sweeps, valid on [10, RGv-10)

    // ---- epilogue: residual + inline LFA + MLP ----
    const float w2pih = 6.28318530717958647692f / 513.0f;
    const float cA = k00 + k22, cB = k02 + k20, cC = k01 + k21, cD = k10 + k12;
    const float sA = k22 - k00, sB = k02 - k20, sC = k21 - k01, sD = k12 - k10;
    float* xo = xout + b * N * N;

    float S1 = 0.f, S2 = 0.f, S3 = ssb2;
    #pragma unroll 8
    for (int j = 0; j < HID; ++j) {
        float wo = lo32(sWo[j]);
        S1 = fmaf(wo, lo32(sWa[j]), S1);
        S2 = fmaf(wo, lo32(sWb[j]), S2);
        S3 = fmaf(wo, lo32(sBb[j]), S3);
    }

    const int etx = tid & 15, ety = tid >> 4;   // 16 x 16 logical
    const int ys_e = HL + ety * 4;
    float s2a[4], c2a[4];
    #pragma unroll
    for (int i = 0; i < 4; ++i)
        __sincosf(w2pih * (float)(gy0v + ys_e + i - 256), &s2a[i], &c2a[i]);

    const ull K1 = pk(0.03567740814f, 0.03567740814f);
    const ull K0 = pk(0.7978845608f,  0.7978845608f);
    const ull Z  = pk(0.f, 0.f);
    float facc = 0.f;   // PHASE 0: ||f||^2 partial

    #pragma unroll 1
    for (int g = 0; g < 4; ++g) {
        const int cx = HL + etx + g*16;
        const int gx = gx0v + cx;
        float s1, c1;
        __sincosf(w2pih * (float)(gx - 256), &s1, &c1);

        const float* rp0 = &cur[(ys_e-1)*RPv + cx];
        float t0 = rp0[-1],    t1 = rp0[0],   t2 = rp0[1];
        float m0 = rp0[RPv-1], m1 = rp0[RPv], m2 = rp0[RPv+1];
        float rl[4], ll[4], xold[4];
        #pragma unroll
        for (int i = 0; i < 4; ++i) {
            const float* nn = rp0 + (i+2)*RPv;
            float n0 = nn[-1], n1 = nn[0], n2 = nn[1];
            float fv_ = fs[(ys_e+i)*RPv + cx];
            if (PHASE == 0) facc = fmaf(fv_, fv_, facc);
            float a1 = fv_;
            a1 = fmaf(nk00,t0,a1); a1 = fmaf(nk01,t1,a1); a1 = fmaf(nk02,t2,a1);
            float a2 = nk10*m0;    a2 = fmaf(nk11,m1,a2); a2 = fmaf(nk12,m2,a2);
            float a3 = nk20*n0;    a3 = fmaf(nk21,n1,a3); a3 = fmaf(nk22,n2,a3);
            rl[i] = a1 + a2 + a3;
            xold[i] = m1;
            float ssv = s1*s2a[i], cc = c1*c2a[i], sc = s1*c2a[i], cs = c1*s2a[i];
            float cpp = cc - ssv, spp = sc + cs;
            float cpm = cc + ssv, spm = sc - cs;
            float ReS = cA*cpp + cB*cpm + cC*c2a[i] + cD*c1 + k11;
            float ImS = sA*spp + sB*spm + sC*s2a[i] + sD*s1;
            float Re = fmaf(-tau, ReS, 1.f);
            float Im = -tau * ImS;
            float mg2 = fmaf(Re, Re, Im*Im);
            ll[i] = mg2 * mg2 * sqrt_ap(mg2);   // |1-tau*S|^5
            t0=m0; t1=m1; t2=m2;
            m0=n0; m1=n1; m2=n2;
        }
        ull Rr0 = pk(rl[0], rl[1]), Rr1 = pk(rl[2], rl[3]);
        ull LF0 = pk(ll[0], ll[1]), LF1 = pk(ll[2], ll[3]);
        ull acc20 = Z, acc21 = Z;
        #pragma unroll 4
        for (int j = 0; j < HID; ++j) {
            const ull wa = sWa[j], wb = sWb[j], bb = sBb[j], wo = sWo[j];
            {
                ull v  = fma2(wa, LF0, fma2(wb, Rr0, bb));
                ull v2 = mul2(v, v);
                ull q  = fma2(v2, K1, K0);
                ull t  = mul2(v, q);
                float tl, th; upk(t, tl, th);
                ull T  = pk(tanh_ap(tl), tanh_ap(th));
                acc20 = fma2(mul2(v, wo), T, acc20);
            }
            {
                ull v  = fma2(wa, LF1, fma2(wb, Rr1, bb));
                ull v2 = mul2(v, v);
                ull q  = fma2(v2, K1, K0);
                ull t  = mul2(v, q);
                float tl, th; upk(t, tl, th);
                ull T  = pk(tanh_ap(tl), tanh_ap(th));
                acc21 = fma2(mul2(v, wo), T, acc21);
            }
        }
        float e0,e1,e2,e3;
        upk(acc20, e0, e1); upk(acc21, e2, e3);
        float ev[4] = {e0, e1, e2, e3};
        #pragma unroll
        for (int i = 0; i < 4; ++i) {
            float u = fmaf(S1, ll[i], fmaf(S2, rl[i], S3));
            float xc = xold[i] + ev[i] + u;
            if (PHASE == 2) nxt[(ys_e + i)*RPv + cx] = xc;
            else            xo[(gy0v + ys_e + i)*N + gx] = xc;
        }
    }

    if (PHASE == 0) {
        __syncthreads();
        block_reduce_add(facc, 1, tid);
        return;
    }

    if (PHASE == 2) {
        // ---- ring pass: corrected x on border of [HL-1, HL+65)^2 (260 pts) ----
        const float K0s = 0.7978845608f, K1s = 0.03567740814f;
        for (int i = tid; i < 260; i += 256) {
            int lx, ly;
            if (i < 66)       { lx = HL-1;            ly = HL-1 + i; }
            else if (i < 132) { lx = HL+64;           ly = HL-1 + (i-66); }
            else if (i < 196) { lx = HL + (i-132);    ly = HL-1; }
            else              { lx = HL + (i-196);    ly = HL+64; }
            int gx = gx0v + lx, gy = gy0v + ly;
            float xc = 0.f;
            if ((unsigned)gx < N && (unsigned)gy < N) {
                const float* c = &cur[ly*RPv + lx];
                float a1 = fs[ly*RPv + lx];
                a1 = fmaf(nk00, c[-RPv-1], a1); a1 = fmaf(nk01, c[-RPv], a1); a1 = fmaf(nk02, c[-RPv+1], a1);
                a1 = fmaf(nk10, c[-1],     a1); a1 = fmaf(nk11, c[0],    a1); a1 = fmaf(nk12, c[1],     a1);
                a1 = fmaf(nk20, c[RPv-1],  a1); a1 = fmaf(nk21, c[RPv],  a1); a1 = fmaf(nk22, c[RPv+1],  a1);
                float r = a1;
                // inline LFA for this point
                float s1r, c1r, s2r, c2r;
                __sincosf(w2pih * (float)(gx - 256), &s1r, &c1r);
                __sincosf(w2pih * (float)(gy - 256), &s2r, &c2r);
                float ssv = s1r*s2r, cc = c1r*c2r, sc = s1r*c2r, cs = c1r*s2r;
                float cpp = cc - ssv, spp = sc + cs;
                float cpm = cc + ssv, spm = sc - cs;
                float ReS = cA*cpp + cB*cpm + cC*c2r + cD*c1r + k11;
                float ImS = sA*spp + sB*spm + sC*s2r + sD*s1r;
                float Re = fmaf(-tau, ReS, 1.f);
                float Im = -tau * ImS;
                float mg2 = fmaf(Re, Re, Im*Im);
                float lf = mg2 * mg2 * sqrt_ap(mg2);
                float acc = fmaf(S1, lf, fmaf(S2, r, S3));
                #pragma unroll 4
                for (int j = 0; j < HID; ++j) {
                    float v = fmaf(lo32(sWa[j]), lf, fmaf(lo32(sWb[j]), r, lo32(sBb[j])));
                    float t = v * fmaf(K1s * v, v, K0s);
                    acc = fmaf(lo32(sWo[j]) * v, tanh_ap(t), acc);
                }
                xc = c[0] + acc;
            }
            nxt[ly*RPv + lx] = xc;
        }
        __syncthreads();

        // ---- fused final residual: ||f - A x_corrected||^2 over tile interior ----
        float racc = 0.f;
        #pragma unroll 1
        for (int g = 0; g < 4; ++g) {
            const int lx = HL + etx + g*16;
            #pragma unroll
            for (int i = 0; i < 4; ++i) {
                const int ly = HL + ety*4 + i;
                const float* c = &nxt[ly*RPv + lx];
                float a1 = fs[ly*RPv + lx];
                a1 = fmaf(nk00, c[-RPv-1], a1); a1 = fmaf(nk01, c[-RPv], a1); a1 = fmaf(nk02, c[-RPv+1], a1);
                a1 = fmaf(nk10, c[-1],     a1); a1 = fmaf(nk11, c[0],    a1); a1 = fmaf(nk12, c[1],     a1);
                a1 = fmaf(nk20, c[RPv-1],  a1); a1 = fmaf(nk21, c[RPv],  a1); a1 = fmaf(nk22, c[RPv+1],  a1);
                racc = fmaf(a1, a1, racc);
            }
        }
        __syncthreads();
        block_reduce_add(racc, 0, tid);
    }
}

__global__ void finalize_kernel(float* out) {
    out[0] = (float)sqrt(g_acc[0] / g_acc[1]);
}

extern "C" void kernel_launch(void* const* d_in, const int* in_sizes, int n_in,
                              void* d_out, int out_size)
{
    // metadata order: f, kernelA, u(unused), W1, b1, W2, b2, epoch(=201 -> K=3)
    const float* f  = (const float*)d_in[0];
    const float* kA = (const float*)d_in[1];
    const float* W1 = (const float*)d_in[3];
    const float* b1 = (const float*)d_in[4];
    const float* W2 = (const float*)d_in[5];
    const float* b2 = (const float*)d_in[6];
    float* out = (float*)d_out;

    const int smem01 = (4 + 3*86*88)*4;   // HALO 11
    const int smem2  = (4 + 3*88*92)*4;   // HALO 12

    cudaFuncSetAttribute(iter_kernel<0>, cudaFuncAttributeMaxDynamicSharedMemorySize, smem01);
    cudaFuncSetAttribute(iter_kernel<1>, cudaFuncAttributeMaxDynamicSharedMemorySize, smem01);
    cudaFuncSetAttribute(iter_kernel<2>, cudaFuncAttributeMaxDynamicSharedMemorySize, smem2);

    dim3 grid(N/TILE, N/TILE, BSZ);   // (8, 8, 16)
    dim3 blk(32, 8);                  // 256 threads

    zero_acc_kernel<<<1, 32>>>();
    // K = 3 outer cycles; x ping-pongs g_x0 <-> g_x1 (starts at zero)
    iter_kernel<0><<<grid, blk, smem01>>>(0, 1, f, kA, W1, b1, W2, b2); // 0 -> x1 (+||f||^2)
    iter_kernel<1><<<grid, blk, smem01>>>(1, 0, f, kA, W1, b1, W2, b2); // x1 -> x0
    iter_kernel<2><<<grid, blk, smem2 >>>(0, 0, f, kA, W1, b1, W2, b2); // x0 -> fused ||r||^2
    finalize_kernel<<<1, 1>>>(out);
}